// round 11
// baseline (speedup 1.0000x reference)
#include <cuda_runtime.h>
#include <cuda_bf16.h>
#include <cuda_fp16.h>
#include <cstdint>
#include <stdint.h>
#include <math.h>

typedef unsigned int u32;

#define N_NODES 20000
#define N_EDGES 320000
#define HID 256
#define HEADS 8
#define HD 32
#define NQKV 768

#define SCAN_BLOCKS 32
#define SCAN_TPB 640           // 20 warps
#define NODES_PER_BLOCK 625    // 32 * 625 = 20000

// head-major permutation: logical col c (= d*8+h) -> h*32+d
__host__ __device__ __forceinline__ int hm_perm(int c) { return (c & 7) * 32 + (c >> 3); }

// ---------------- scratch (device globals; no allocation allowed) ----------
__device__ __align__(16) float  g_q[N_NODES * HID];          // Q fp32 (head-major)
__device__ __align__(16) __half g_kv[N_NODES * 512];         // K|V fp16 (head-major)
__device__ __align__(16) __nv_bfloat16 g_h_hi[N_NODES * HID];
__device__ __align__(16) __nv_bfloat16 g_h_lo[N_NODES * HID];
__device__ __align__(16) __nv_bfloat16 g_ao_hi[N_NODES * HID];  // head-major
__device__ __align__(16) __nv_bfloat16 g_ao_lo[N_NODES * HID];
__device__ __align__(16) __nv_bfloat16 g_wc_hi[HID * NQKV];  // cols permuted head-major
__device__ __align__(16) __nv_bfloat16 g_wc_lo[HID * NQKV];
__device__ __align__(16) __nv_bfloat16 g_wo_hi[HID * HID];   // rows permuted head-major
__device__ __align__(16) __nv_bfloat16 g_wo_lo[HID * HID];
__device__ __align__(16) float g_bias3[NQKV];                // permuted head-major
__device__ int g_cnt[N_NODES];
__device__ int g_rowptr[N_NODES + 1];
__device__ int g_woff[N_NODES];
__device__ int g_cols[N_EDGES];
__device__ volatile int g_agg[SCAN_BLOCKS];
__device__ volatile int g_flag[SCAN_BLOCKS];

// ---------------- fused prep: h split + W split(+permute) + bias + zero ----
__global__ void k_prep(const float4* __restrict__ x,
                       const float4* __restrict__ Wq, const float4* __restrict__ Wk,
                       const float4* __restrict__ Wv, const float4* __restrict__ Wo,
                       const float* __restrict__ bq, const float* __restrict__ bk,
                       const float* __restrict__ bv, int n4h)
{
    int i = blockIdx.x * blockDim.x + threadIdx.x;
    if (i < N_NODES) g_cnt[i] = 0;
    if (i < NQKV) {
        int region = i >> 8;        // 0=q 1=k 2=v
        int c = i & 255;
        const float* b = (region == 0) ? bq : (region == 1) ? bk : bv;
        g_bias3[region * 256 + hm_perm(c)] = b[c];
    }

    if (i < 4 * 16384) {
        int widx = i >> 14;
        int j = i & 16383;
        const float4* src = (widx == 0) ? Wq : (widx == 1) ? Wk : (widx == 2) ? Wv : Wo;
        float4 v = src[j];
        float f[4];
        f[0] = v.x; f[1] = v.y; f[2] = v.z; f[3] = v.w;
        __align__(8) __nv_bfloat16 h[4];
        __align__(8) __nv_bfloat16 l[4];
#pragma unroll
        for (int t = 0; t < 4; t++) {
            h[t] = __float2bfloat16(f[t]);
            l[t] = __float2bfloat16(f[t] - __bfloat162float(h[t]));
        }
        int kr = j >> 6;        // row 0..255
        int n4 = j & 63;        // float4-col group
        if (widx < 3) {
            // permute COLUMNS to head-major: scattered 2B writes (tiny matrix)
#pragma unroll
            for (int t = 0; t < 4; t++) {
                int cc = hm_perm(n4 * 4 + t);
                int o = kr * NQKV + widx * 256 + cc;
                g_wc_hi[o] = h[t];
                g_wc_lo[o] = l[t];
            }
        } else {
            // permute ROWS to head-major: row stays contiguous -> coalesced
            int rr = hm_perm(kr);
            int o = rr * 64 + n4;
            ((uint2*)g_wo_hi)[o] = *(uint2*)h;
            ((uint2*)g_wo_lo)[o] = *(uint2*)l;
        }
    }

    if (i < n4h) {
        float4 v = x[i];
        float f[4];
        f[0] = v.x; f[1] = v.y; f[2] = v.z; f[3] = v.w;
        __align__(8) __nv_bfloat16 h[4];
        __align__(8) __nv_bfloat16 l[4];
#pragma unroll
        for (int j = 0; j < 4; j++) {
            h[j] = __float2bfloat16(f[j]);
            l[j] = __float2bfloat16(f[j] - __bfloat162float(h[j]));
        }
        ((uint2*)g_h_hi)[i] = *(uint2*)h;
        ((uint2*)g_h_lo)[i] = *(uint2*)l;
    }
}

// ---------------- split-bf16 tensor-core GEMM (cp.async 2-stage, 1 sync) ----
#define BM 128
#define BN 128
#define BK 32
#define STA 40
#define STW 136
#define NIT (HID / BK)
#define A_OFF(st, hl) (((st) * 2 + (hl)) * 5120)
#define W_OFF(st, hl) (20480 + ((st) * 2 + (hl)) * 4352)
#define GEMM_SMEM_BYTES ((20480 + 17408) * 2)

__device__ __forceinline__ void ldm_x4(u32* r, u32 addr) {
    asm volatile("ldmatrix.sync.aligned.m8n8.x4.shared.b16 {%0,%1,%2,%3}, [%4];"
                 : "=r"(r[0]), "=r"(r[1]), "=r"(r[2]), "=r"(r[3]) : "r"(addr));
}
__device__ __forceinline__ void ldm_x4t(u32* r, u32 addr) {
    asm volatile("ldmatrix.sync.aligned.m8n8.x4.trans.shared.b16 {%0,%1,%2,%3}, [%4];"
                 : "=r"(r[0]), "=r"(r[1]), "=r"(r[2]), "=r"(r[3]) : "r"(addr));
}
__device__ __forceinline__ void mma16816(float* c, const u32* a, const u32* b) {
    asm volatile("mma.sync.aligned.m16n8k16.row.col.f32.bf16.bf16.f32 "
                 "{%0,%1,%2,%3}, {%4,%5,%6,%7}, {%8,%9}, {%0,%1,%2,%3};"
                 : "+f"(c[0]), "+f"(c[1]), "+f"(c[2]), "+f"(c[3])
                 : "r"(a[0]), "r"(a[1]), "r"(a[2]), "r"(a[3]), "r"(b[0]), "r"(b[1]));
}
__device__ __forceinline__ void cpa16(u32 dst, const void* src, int bytes) {
    asm volatile("cp.async.cg.shared.global [%0], [%1], 16, %2;"
                 :: "r"(dst), "l"(src), "r"(bytes));
}

__global__ __launch_bounds__(256) void hgemm_split(
    const __nv_bfloat16* __restrict__ Ahi, const __nv_bfloat16* __restrict__ Alo,
    const __nv_bfloat16* __restrict__ Whi, const __nv_bfloat16* __restrict__ Wlo,
    const float* __restrict__ bias, float* __restrict__ Cq, __half* __restrict__ Ckv,
    int M, int NTOT)
{
    extern __shared__ __align__(16) __nv_bfloat16 smem[];
    u32 smB = (u32)__cvta_generic_to_shared(smem);

    int tid = threadIdx.x;
    int lane = tid & 31;
    int wid = tid >> 5;
    int mwarp = (wid >> 2) * 64;
    int nwarp = (wid & 3) * 32;
    int blockM = blockIdx.x * BM;
    int blockN = blockIdx.y * BN;

    int rA[2], kcA[2], grA[2], krW[2], ncW[2];
#pragma unroll
    for (int it = 0; it < 2; it++) {
        int idx = tid + it * 256;
        rA[it] = idx >> 2;  kcA[it] = idx & 3;  grA[it] = blockM + rA[it];
        krW[it] = idx >> 4; ncW[it] = idx & 15;
    }

    float acc[4][4][4];
#pragma unroll
    for (int mt = 0; mt < 4; mt++)
#pragma unroll
        for (int nt = 0; nt < 4; nt++)
#pragma unroll
            for (int j = 0; j < 4; j++) acc[mt][nt][j] = 0.f;

    int rowA = (lane & 7) + ((lane >> 3) & 1) * 8;
    int offA = rowA * (STA * 2) + (lane >> 4) * 16;
    int offB4 = ((lane & 7) + ((lane >> 3) & 1) * 8) * (STW * 2) + ((lane >> 4) & 1) * 16;

#define LOAD_STAGE(st, k0base)                                                     \
    do {                                                                           \
        _Pragma("unroll")                                                          \
        for (int it = 0; it < 2; it++) {                                           \
            int pb = (grA[it] < M) ? 16 : 0;                                       \
            u32 dAh = smB + (u32)(A_OFF(st, 0) + rA[it] * STA + kcA[it] * 8) * 2;  \
            u32 dAl = smB + (u32)(A_OFF(st, 1) + rA[it] * STA + kcA[it] * 8) * 2;  \
            cpa16(dAh, Ahi + grA[it] * HID + (k0base) + kcA[it] * 8, pb);          \
            cpa16(dAl, Alo + grA[it] * HID + (k0base) + kcA[it] * 8, pb);          \
            u32 dWh = smB + (u32)(W_OFF(st, 0) + krW[it] * STW + ncW[it] * 8) * 2; \
            u32 dWl = smB + (u32)(W_OFF(st, 1) + krW[it] * STW + ncW[it] * 8) * 2; \
            cpa16(dWh, Whi + ((k0base) + krW[it]) * NTOT + blockN + ncW[it] * 8, 16); \
            cpa16(dWl, Wlo + ((k0base) + krW[it]) * NTOT + blockN + ncW[it] * 8, 16); \
        }                                                                          \
        asm volatile("cp.async.commit_group;");                                    \
    } while (0)

#define MMA_STAGE(st)                                                              \
    do {                                                                           \
        _Pragma("unroll")                                                          \
        for (int kk = 0; kk < 2; kk++) {                                           \
            u32 ahi[4][4], alo[4][4], bhi[4][2], blo[4][2];                        \
            _Pragma("unroll")                                                      \
            for (int mt = 0; mt < 4; mt++) {                                       \
                u32 o = (u32)((mwarp + mt * 16) * (STA * 2) + kk * 32 + offA);     \
                ldm_x4(ahi[mt], smB + (u32)A_OFF(st, 0) * 2 + o);                  \
                ldm_x4(alo[mt], smB + (u32)A_OFF(st, 1) * 2 + o);                  \
            }                                                                      \
            _Pragma("unroll")                                                      \
            for (int np = 0; np < 2; np++) {                                       \
                u32 o = (u32)(kk * 16 * (STW * 2) + offB4 + (nwarp + np * 16) * 2);\
                u32 rh[4], rl[4];                                                  \
                ldm_x4t(rh, smB + (u32)W_OFF(st, 0) * 2 + o);                      \
                ldm_x4t(rl, smB + (u32)W_OFF(st, 1) * 2 + o);                      \
                bhi[np * 2][0] = rh[0]; bhi[np * 2][1] = rh[1];                    \
                bhi[np * 2 + 1][0] = rh[2]; bhi[np * 2 + 1][1] = rh[3];            \
                blo[np * 2][0] = rl[0]; blo[np * 2][1] = rl[1];                    \
                blo[np * 2 + 1][0] = rl[2]; blo[np * 2 + 1][1] = rl[3];            \
            }                                                                      \
            _Pragma("unroll")                                                      \
            for (int mt = 0; mt < 4; mt++) {                                       \
                _Pragma("unroll")                                                  \
                for (int nt = 0; nt < 4; nt++) {                                   \
                    mma16816(acc[mt][nt], ahi[mt], bhi[nt]);                       \
                    mma16816(acc[mt][nt], ahi[mt], blo[nt]);                       \
                    mma16816(acc[mt][nt], alo[mt], bhi[nt]);                       \
                }                                                                  \
            }                                                                      \
        }                                                                          \
    } while (0)

    LOAD_STAGE(0, 0);
#pragma unroll 1
    for (int i = 0; i < NIT; i++) {
        asm volatile("cp.async.wait_group 0;");
        __syncthreads();
        if (i + 1 < NIT) LOAD_STAGE((i + 1) & 1, (i + 1) * BK);
        MMA_STAGE(i & 1);
    }

    // epilogue: + bias, route Q (fp32) vs KV (fp16)
    int g = lane >> 2;
    int t4 = lane & 3;
#pragma unroll
    for (int mt = 0; mt < 4; mt++) {
        int row0 = blockM + mwarp + mt * 16 + g;
        int row1 = row0 + 8;
#pragma unroll
        for (int nt = 0; nt < 4; nt++) {
            int col = blockN + nwarp + nt * 8 + t4 * 2;
            float b0 = bias[col];
            float b1 = bias[col + 1];
            float c00 = acc[mt][nt][0] + b0, c01 = acc[mt][nt][1] + b1;
            float c10 = acc[mt][nt][2] + b0, c11 = acc[mt][nt][3] + b1;
            if (col < 256) {
                if (row0 < M) *(float2*)(Cq + row0 * 256 + col) = make_float2(c00, c01);
                if (row1 < M) *(float2*)(Cq + row1 * 256 + col) = make_float2(c10, c11);
            } else {
                int kc = col - 256;
                if (row0 < M) *(__half2*)(Ckv + row0 * 512 + kc) = __floats2half2_rn(c00, c01);
                if (row1 < M) *(__half2*)(Ckv + row1 * 512 + kc) = __floats2half2_rn(c10, c11);
            }
        }
    }
}

// ---------------- CSR build ------------------------------------------------
__global__ void k_hist(const int4* __restrict__ rows4) {
    int i = blockIdx.x * blockDim.x + threadIdx.x;
    if (i < SCAN_BLOCKS) { g_flag[i] = 0; }
    if (i < N_EDGES / 4) {
        int4 r = rows4[i];
        atomicAdd(&g_cnt[r.x], 1);
        atomicAdd(&g_cnt[r.y], 1);
        atomicAdd(&g_cnt[r.z], 1);
        atomicAdd(&g_cnt[r.w], 1);
    }
}

__global__ __launch_bounds__(SCAN_TPB) void k_scan() {
    int b = blockIdx.x;
    int tid = threadIdx.x;
    int lane = tid & 31;
    int wid = tid >> 5;
    int idx = b * NODES_PER_BLOCK + tid;

    int c = (tid < NODES_PER_BLOCK && idx < N_NODES) ? g_cnt[idx] : 0;

    int v = c;
#pragma unroll
    for (int off = 1; off < 32; off <<= 1) {
        int t = __shfl_up_sync(0xffffffffu, v, off);
        if (lane >= off) v += t;
    }
    __shared__ int ws[20];
    if (lane == 31) ws[wid] = v;
    __syncthreads();
    if (wid == 0) {
        int x = (lane < 20) ? ws[lane] : 0;
#pragma unroll
        for (int off = 1; off < 32; off <<= 1) {
            int t = __shfl_up_sync(0xffffffffu, x, off);
            if (lane >= off) x += t;
        }
        if (lane < 20) ws[lane] = x;
    }
    __syncthreads();
    int incl = v + ((wid > 0) ? ws[wid - 1] : 0);
    int btotal = ws[19];

    __shared__ int s_excl;
    if (tid == 0) {
        g_agg[b] = btotal;
        __threadfence();
        g_flag[b] = 1;
    }
    if (wid == 0) {
        int sum = 0;
        if (lane < b) {
            while (g_flag[lane] == 0) { }
            sum = g_agg[lane];
        }
#pragma unroll
        for (int off = 16; off > 0; off >>= 1)
            sum += __shfl_xor_sync(0xffffffffu, sum, off);
        if (lane == 0) s_excl = sum;
    }
    __syncthreads();
    int excl_blk = s_excl;

    if (tid < NODES_PER_BLOCK && idx < N_NODES) {
        int o = excl_blk + incl - c;
        g_rowptr[idx] = o;
        g_woff[idx] = o;
    }
    if (b == SCAN_BLOCKS - 1 && tid == 0)
        g_rowptr[N_NODES] = excl_blk + btotal;
}

__global__ void k_scatter(const int4* __restrict__ rows4, const int4* __restrict__ cols4) {
    int i = blockIdx.x * blockDim.x + threadIdx.x;
    if (i >= N_EDGES / 4) return;
    int4 r = rows4[i];
    int4 c = cols4[i];
    g_cols[atomicAdd(&g_woff[r.x], 1)] = c.x;
    g_cols[atomicAdd(&g_woff[r.y], 1)] = c.y;
    g_cols[atomicAdd(&g_woff[r.z], 1)] = c.z;
    g_cols[atomicAdd(&g_woff[r.w], 1)] = c.w;
}

// ---------------- fused SDDMM + softmax + SpMM (head-major, fp16 K/V) -------
// lane -> head h = lane/4, dim slice = (lane%4)*8. All loads coalesced.
// Score reduce = 2 shuffles in the 4-lane group; 1 exp per edge.
__global__ __launch_bounds__(256) void attn_kernel() {
    int gw = (blockIdx.x * blockDim.x + threadIdx.x) >> 5;
    int lane = threadIdx.x & 31;
    if (gw >= N_NODES) return;
    int row = gw;
    int p0 = g_rowptr[row];
    int p1 = g_rowptr[row + 1];

    const float scaling = 0.1767766952966369f;  // 1/sqrt(32)
    const float4* qp = (const float4*)(g_q + row * HID + lane * 8);
    float4 q0 = qp[0];
    float4 q1 = qp[1];
    float qv[8];
    qv[0] = q0.x * scaling; qv[1] = q0.y * scaling; qv[2] = q0.z * scaling; qv[3] = q0.w * scaling;
    qv[4] = q1.x * scaling; qv[5] = q1.y * scaling; qv[6] = q1.z * scaling; qv[7] = q1.w * scaling;

    float z = 0.f;
    float acc[8];
#pragma unroll
    for (int j = 0; j < 8; j++) acc[j] = 0.f;

    if (p0 < p1) {
        // 2-deep pipeline
        int col = g_cols[p0];
        uint4 kr = *(const uint4*)(g_kv + col * 512 + lane * 8);        // 8 K halves
        uint4 vr = *(const uint4*)(g_kv + col * 512 + 256 + lane * 8);  // 8 V halves

        for (int p = p0; p < p1; p++) {
            uint4 kc = kr, vc = vr;
            if (p + 1 < p1) {
                int col2 = g_cols[p + 1];
                kr = *(const uint4*)(g_kv + col2 * 512 + lane * 8);
                vr = *(const uint4*)(g_kv + col2 * 512 + 256 + lane * 8);
            }

            const __half2* kh = (const __half2*)&kc;
            float2 k01 = __half22float2(kh[0]);
            float2 k23 = __half22float2(kh[1]);
            float2 k45 = __half22float2(kh[2]);
            float2 k67 = __half22float2(kh[3]);

            float s = qv[0] * k01.x;
            s = fmaf(qv[1], k01.y, s);
            s = fmaf(qv[2], k23.x, s);
            s = fmaf(qv[3], k23.y, s);
            s = fmaf(qv[4], k45.x, s);
            s = fmaf(qv[5], k45.y, s);
            s = fmaf(qv[6], k67.x, s);
            s = fmaf(qv[7], k67.y, s);

            // reduce within the 4-lane head group
            s += __shfl_xor_sync(0xffffffffu, s, 1);
            s += __shfl_xor_sync(0xffffffffu, s, 2);

            float pr = __expf(s);
            z += pr;

            const __half2* vh = (const __half2*)&vc;
            float2 v01 = __half22float2(vh[0]);
            float2 v23 = __half22float2(vh[1]);
            float2 v45 = __half22float2(vh[2]);
            float2 v67 = __half22float2(vh[3]);
            acc[0] = fmaf(pr, v01.x, acc[0]);
            acc[1] = fmaf(pr, v01.y, acc[1]);
            acc[2] = fmaf(pr, v23.x, acc[2]);
            acc[3] = fmaf(pr, v23.y, acc[3]);
            acc[4] = fmaf(pr, v45.x, acc[4]);
            acc[5] = fmaf(pr, v45.y, acc[5]);
            acc[6] = fmaf(pr, v67.x, acc[6]);
            acc[7] = fmaf(pr, v67.y, acc[7]);
        }
    }

    float out[8];
    bool has = (p1 > p0);
    float inv = has ? 1.0f / z : 0.f;
#pragma unroll
    for (int j = 0; j < 8; j++) out[j] = acc[j] * inv;

    __align__(16) __nv_bfloat16 hi[8];
    __align__(16) __nv_bfloat16 lo[8];
#pragma unroll
    for (int j = 0; j < 8; j++) {
        hi[j] = __float2bfloat16(out[j]);
        lo[j] = __float2bfloat16(out[j] - __bfloat162float(hi[j]));
    }
    *(uint4*)(g_ao_hi + row * HID + lane * 8) = *(uint4*)hi;
    *(uint4*)(g_ao_lo + row * HID + lane * 8) = *(uint4*)lo;
}

// ---------------- launch ---------------------------------------------------
extern "C" void kernel_launch(void* const* d_in, const int* in_sizes, int n_in,
                              void* d_out, int out_size)
{
    const float* h  = (const float*)d_in[0];
    const float* Wq = (const float*)d_in[1];
    const float* bq = (const float*)d_in[2];
    const float* Wk = (const float*)d_in[3];
    const float* bk = (const float*)d_in[4];
    const float* Wv = (const float*)d_in[5];
    const float* bv = (const float*)d_in[6];
    const float* Wo = (const float*)d_in[7];
    const float* bo = (const float*)d_in[8];
    const int* rows = (const int*)d_in[9];
    const int* cols = (const int*)d_in[10];
    float* out = (float*)d_out;

    float *q, *bias3;
    __half* kv;
    __nv_bfloat16 *h_hi, *h_lo, *ao_hi, *ao_lo, *wc_hi, *wc_lo, *wo_hi, *wo_lo;
    cudaGetSymbolAddress((void**)&q,     g_q);
    cudaGetSymbolAddress((void**)&kv,    g_kv);
    cudaGetSymbolAddress((void**)&bias3, g_bias3);
    cudaGetSymbolAddress((void**)&h_hi,  g_h_hi);
    cudaGetSymbolAddress((void**)&h_lo,  g_h_lo);
    cudaGetSymbolAddress((void**)&ao_hi, g_ao_hi);
    cudaGetSymbolAddress((void**)&ao_lo, g_ao_lo);
    cudaGetSymbolAddress((void**)&wc_hi, g_wc_hi);
    cudaGetSymbolAddress((void**)&wc_lo, g_wc_lo);
    cudaGetSymbolAddress((void**)&wo_hi, g_wo_hi);
    cudaGetSymbolAddress((void**)&wo_lo, g_wo_lo);

    static int smem_set = 0;
    if (!smem_set) {
        cudaFuncSetAttribute(hgemm_split, cudaFuncAttributeMaxDynamicSharedMemorySize,
                             GEMM_SMEM_BYTES);
        smem_set = 1;
    }

    int n4h = (N_NODES * HID) / 4;

    k_prep<<<(n4h + 255) / 256, 256>>>((const float4*)h, (const float4*)Wq,
                                       (const float4*)Wk, (const float4*)Wv,
                                       (const float4*)Wo, bq, bk, bv, n4h);

    dim3 gqkv((N_NODES + BM - 1) / BM, NQKV / BN);
    hgemm_split<<<gqkv, 256, GEMM_SMEM_BYTES>>>(h_hi, h_lo, wc_hi, wc_lo, bias3,
                                                q, kv, N_NODES, NQKV);

    k_hist<<<(N_EDGES / 4 + 255) / 256, 256>>>((const int4*)rows);
    k_scan<<<SCAN_BLOCKS, SCAN_TPB>>>();
    k_scatter<<<(N_EDGES / 4 + 255) / 256, 256>>>((const int4*)rows, (const int4*)cols);

    attn_kernel<<<(N_NODES * 32 + 255) / 256, 256>>>();

    dim3 go((N_NODES + BM - 1) / BM, HID / BN);
    hgemm_split<<<go, 256, GEMM_SMEM_BYTES>>>(ao_hi, ao_lo, wo_hi, wo_lo, bo,
                                              out, (__half*)nullptr, N_NODES, HID);
}

// round 12
// speedup vs baseline: 1.0006x; 1.0006x over previous
#include <cuda_runtime.h>
#include <cuda_bf16.h>
#include <cuda_fp16.h>
#include <cstdint>
#include <stdint.h>
#include <math.h>

typedef unsigned int u32;

#define N_NODES 20000
#define N_EDGES 320000
#define HID 256
#define HEADS 8
#define HD 32
#define NQKV 768

#define SCAN_BLOCKS 32
#define SCAN_TPB 640           // 20 warps
#define NODES_PER_BLOCK 625    // 32 * 625 = 20000

// head-major permutation: logical col c (= d*8+h) -> h*32+d
__host__ __device__ __forceinline__ int hm_perm(int c) { return (c & 7) * 32 + (c >> 3); }

// ---------------- scratch (device globals; no allocation allowed) ----------
__device__ __align__(16) float  g_q[N_NODES * HID];          // Q fp32 (head-major)
__device__ __align__(16) __half g_kv[N_NODES * 512];         // K|V fp16 (head-major)
__device__ __align__(16) __nv_bfloat16 g_h_hi[N_NODES * HID];
__device__ __align__(16) __nv_bfloat16 g_h_lo[N_NODES * HID];
__device__ __align__(16) __nv_bfloat16 g_ao_hi[N_NODES * HID];  // head-major
__device__ __align__(16) __nv_bfloat16 g_ao_lo[N_NODES * HID];
__device__ __align__(16) __nv_bfloat16 g_wc_hi[HID * NQKV];  // cols permuted head-major
__device__ __align__(16) __nv_bfloat16 g_wc_lo[HID * NQKV];
__device__ __align__(16) __nv_bfloat16 g_wo_hi[HID * HID];   // rows permuted head-major
__device__ __align__(16) __nv_bfloat16 g_wo_lo[HID * HID];
__device__ __align__(16) float g_bias3[NQKV];                // permuted head-major
__device__ int g_cnt[N_NODES];
__device__ int g_rowptr[N_NODES + 1];
__device__ int g_woff[N_NODES];
__device__ int g_cols[N_EDGES];
__device__ volatile int g_agg[SCAN_BLOCKS];
__device__ volatile int g_flag[SCAN_BLOCKS];

// ---------------- fused prep: h split + W split(+permute) + bias + zero ----
__global__ void k_prep(const float4* __restrict__ x,
                       const float4* __restrict__ Wq, const float4* __restrict__ Wk,
                       const float4* __restrict__ Wv, const float4* __restrict__ Wo,
                       const float* __restrict__ bq, const float* __restrict__ bk,
                       const float* __restrict__ bv, int n4h)
{
    int i = blockIdx.x * blockDim.x + threadIdx.x;
    if (i < N_NODES) g_cnt[i] = 0;
    if (i < NQKV) {
        int region = i >> 8;        // 0=q 1=k 2=v
        int c = i & 255;
        const float* b = (region == 0) ? bq : (region == 1) ? bk : bv;
        g_bias3[region * 256 + hm_perm(c)] = b[c];
    }

    if (i < 4 * 16384) {
        int widx = i >> 14;
        int j = i & 16383;
        const float4* src = (widx == 0) ? Wq : (widx == 1) ? Wk : (widx == 2) ? Wv : Wo;
        float4 v = src[j];
        float f[4];
        f[0] = v.x; f[1] = v.y; f[2] = v.z; f[3] = v.w;
        __align__(8) __nv_bfloat16 h[4];
        __align__(8) __nv_bfloat16 l[4];
#pragma unroll
        for (int t = 0; t < 4; t++) {
            h[t] = __float2bfloat16(f[t]);
            l[t] = __float2bfloat16(f[t] - __bfloat162float(h[t]));
        }
        int kr = j >> 6;        // row 0..255
        int n4 = j & 63;        // float4-col group
        if (widx < 3) {
            // permute COLUMNS to head-major: scattered 2B writes (tiny matrix)
#pragma unroll
            for (int t = 0; t < 4; t++) {
                int cc = hm_perm(n4 * 4 + t);
                int o = kr * NQKV + widx * 256 + cc;
                g_wc_hi[o] = h[t];
                g_wc_lo[o] = l[t];
            }
        } else {
            // permute ROWS to head-major: row stays contiguous -> coalesced
            int rr = hm_perm(kr);
            int o = rr * 64 + n4;
            ((uint2*)g_wo_hi)[o] = *(uint2*)h;
            ((uint2*)g_wo_lo)[o] = *(uint2*)l;
        }
    }

    if (i < n4h) {
        float4 v = x[i];
        float f[4];
        f[0] = v.x; f[1] = v.y; f[2] = v.z; f[3] = v.w;
        __align__(8) __nv_bfloat16 h[4];
        __align__(8) __nv_bfloat16 l[4];
#pragma unroll
        for (int j = 0; j < 4; j++) {
            h[j] = __float2bfloat16(f[j]);
            l[j] = __float2bfloat16(f[j] - __bfloat162float(h[j]));
        }
        ((uint2*)g_h_hi)[i] = *(uint2*)h;
        ((uint2*)g_h_lo)[i] = *(uint2*)l;
    }
}

// ---------------- split-bf16 tensor-core GEMM (cp.async 2-stage, 1 sync) ----
#define BM 128
#define BN 128
#define BK 32
#define STA 40
#define STW 136
#define NIT (HID / BK)
#define A_OFF(st, hl) (((st) * 2 + (hl)) * 5120)
#define W_OFF(st, hl) (20480 + ((st) * 2 + (hl)) * 4352)
#define GEMM_SMEM_BYTES ((20480 + 17408) * 2)

__device__ __forceinline__ void ldm_x4(u32* r, u32 addr) {
    asm volatile("ldmatrix.sync.aligned.m8n8.x4.shared.b16 {%0,%1,%2,%3}, [%4];"
                 : "=r"(r[0]), "=r"(r[1]), "=r"(r[2]), "=r"(r[3]) : "r"(addr));
}
__device__ __forceinline__ void ldm_x4t(u32* r, u32 addr) {
    asm volatile("ldmatrix.sync.aligned.m8n8.x4.trans.shared.b16 {%0,%1,%2,%3}, [%4];"
                 : "=r"(r[0]), "=r"(r[1]), "=r"(r[2]), "=r"(r[3]) : "r"(addr));
}
__device__ __forceinline__ void mma16816(float* c, const u32* a, const u32* b) {
    asm volatile("mma.sync.aligned.m16n8k16.row.col.f32.bf16.bf16.f32 "
                 "{%0,%1,%2,%3}, {%4,%5,%6,%7}, {%8,%9}, {%0,%1,%2,%3};"
                 : "+f"(c[0]), "+f"(c[1]), "+f"(c[2]), "+f"(c[3])
                 : "r"(a[0]), "r"(a[1]), "r"(a[2]), "r"(a[3]), "r"(b[0]), "r"(b[1]));
}
__device__ __forceinline__ void cpa16(u32 dst, const void* src, int bytes) {
    asm volatile("cp.async.cg.shared.global [%0], [%1], 16, %2;"
                 :: "r"(dst), "l"(src), "r"(bytes));
}

__global__ __launch_bounds__(256) void hgemm_split(
    const __nv_bfloat16* __restrict__ Ahi, const __nv_bfloat16* __restrict__ Alo,
    const __nv_bfloat16* __restrict__ Whi, const __nv_bfloat16* __restrict__ Wlo,
    const float* __restrict__ bias, float* __restrict__ Cq, __half* __restrict__ Ckv,
    int M, int NTOT)
{
    extern __shared__ __align__(16) __nv_bfloat16 smem[];
    u32 smB = (u32)__cvta_generic_to_shared(smem);

    int tid = threadIdx.x;
    int lane = tid & 31;
    int wid = tid >> 5;
    int mwarp = (wid >> 2) * 64;
    int nwarp = (wid & 3) * 32;
    int blockM = blockIdx.x * BM;
    int blockN = blockIdx.y * BN;

    int rA[2], kcA[2], grA[2], krW[2], ncW[2];
#pragma unroll
    for (int it = 0; it < 2; it++) {
        int idx = tid + it * 256;
        rA[it] = idx >> 2;  kcA[it] = idx & 3;  grA[it] = blockM + rA[it];
        krW[it] = idx >> 4; ncW[it] = idx & 15;
    }

    float acc[4][4][4];
#pragma unroll
    for (int mt = 0; mt < 4; mt++)
#pragma unroll
        for (int nt = 0; nt < 4; nt++)
#pragma unroll
            for (int j = 0; j < 4; j++) acc[mt][nt][j] = 0.f;

    int rowA = (lane & 7) + ((lane >> 3) & 1) * 8;
    int offA = rowA * (STA * 2) + (lane >> 4) * 16;
    int offB4 = ((lane & 7) + ((lane >> 3) & 1) * 8) * (STW * 2) + ((lane >> 4) & 1) * 16;

#define LOAD_STAGE(st, k0base)                                                     \
    do {                                                                           \
        _Pragma("unroll")                                                          \
        for (int it = 0; it < 2; it++) {                                           \
            int pb = (grA[it] < M) ? 16 : 0;                                       \
            u32 dAh = smB + (u32)(A_OFF(st, 0) + rA[it] * STA + kcA[it] * 8) * 2;  \
            u32 dAl = smB + (u32)(A_OFF(st, 1) + rA[it] * STA + kcA[it] * 8) * 2;  \
            cpa16(dAh, Ahi + grA[it] * HID + (k0base) + kcA[it] * 8, pb);          \
            cpa16(dAl, Alo + grA[it] * HID + (k0base) + kcA[it] * 8, pb);          \
            u32 dWh = smB + (u32)(W_OFF(st, 0) + krW[it] * STW + ncW[it] * 8) * 2; \
            u32 dWl = smB + (u32)(W_OFF(st, 1) + krW[it] * STW + ncW[it] * 8) * 2; \
            cpa16(dWh, Whi + ((k0base) + krW[it]) * NTOT + blockN + ncW[it] * 8, 16); \
            cpa16(dWl, Wlo + ((k0base) + krW[it]) * NTOT + blockN + ncW[it] * 8, 16); \
        }                                                                          \
        asm volatile("cp.async.commit_group;");                                    \
    } while (0)

#define MMA_STAGE(st)                                                              \
    do {                                                                           \
        _Pragma("unroll")                                                          \
        for (int kk = 0; kk < 2; kk++) {                                           \
            u32 ahi[4][4], alo[4][4], bhi[4][2], blo[4][2];                        \
            _Pragma("unroll")                                                      \
            for (int mt = 0; mt < 4; mt++) {                                       \
                u32 o = (u32)((mwarp + mt * 16) * (STA * 2) + kk * 32 + offA);     \
                ldm_x4(ahi[mt], smB + (u32)A_OFF(st, 0) * 2 + o);                  \
                ldm_x4(alo[mt], smB + (u32)A_OFF(st, 1) * 2 + o);                  \
            }                                                                      \
            _Pragma("unroll")                                                      \
            for (int np = 0; np < 2; np++) {                                       \
                u32 o = (u32)(kk * 16 * (STW * 2) + offB4 + (nwarp + np * 16) * 2);\
                u32 rh[4], rl[4];                                                  \
                ldm_x4t(rh, smB + (u32)W_OFF(st, 0) * 2 + o);                      \
                ldm_x4t(rl, smB + (u32)W_OFF(st, 1) * 2 + o);                      \
                bhi[np * 2][0] = rh[0]; bhi[np * 2][1] = rh[1];                    \
                bhi[np * 2 + 1][0] = rh[2]; bhi[np * 2 + 1][1] = rh[3];            \
                blo[np * 2][0] = rl[0]; blo[np * 2][1] = rl[1];                    \
                blo[np * 2 + 1][0] = rl[2]; blo[np * 2 + 1][1] = rl[3];            \
            }                                                                      \
            _Pragma("unroll")                                                      \
            for (int mt = 0; mt < 4; mt++) {                                       \
                _Pragma("unroll")                                                  \
                for (int nt = 0; nt < 4; nt++) {                                   \
                    mma16816(acc[mt][nt], ahi[mt], bhi[nt]);                       \
                    mma16816(acc[mt][nt], ahi[mt], blo[nt]);                       \
                    mma16816(acc[mt][nt], alo[mt], bhi[nt]);                       \
                }                                                                  \
            }                                                                      \
        }                                                                          \
    } while (0)

    LOAD_STAGE(0, 0);
#pragma unroll 1
    for (int i = 0; i < NIT; i++) {
        asm volatile("cp.async.wait_group 0;");
        __syncthreads();
        if (i + 1 < NIT) LOAD_STAGE((i + 1) & 1, (i + 1) * BK);
        MMA_STAGE(i & 1);
    }

    // epilogue: + bias, route Q (fp32) vs KV (fp16)
    int g = lane >> 2;
    int t4 = lane & 3;
#pragma unroll
    for (int mt = 0; mt < 4; mt++) {
        int row0 = blockM + mwarp + mt * 16 + g;
        int row1 = row0 + 8;
#pragma unroll
        for (int nt = 0; nt < 4; nt++) {
            int col = blockN + nwarp + nt * 8 + t4 * 2;
            float b0 = bias[col];
            float b1 = bias[col + 1];
            float c00 = acc[mt][nt][0] + b0, c01 = acc[mt][nt][1] + b1;
            float c10 = acc[mt][nt][2] + b0, c11 = acc[mt][nt][3] + b1;
            if (col < 256) {
                if (row0 < M) *(float2*)(Cq + row0 * 256 + col) = make_float2(c00, c01);
                if (row1 < M) *(float2*)(Cq + row1 * 256 + col) = make_float2(c10, c11);
            } else {
                int kc = col - 256;
                if (row0 < M) *(__half2*)(Ckv + row0 * 512 + kc) = __floats2half2_rn(c00, c01);
                if (row1 < M) *(__half2*)(Ckv + row1 * 512 + kc) = __floats2half2_rn(c10, c11);
            }
        }
    }
}

// ---------------- CSR build ------------------------------------------------
__global__ void k_hist(const int4* __restrict__ rows4) {
    int i = blockIdx.x * blockDim.x + threadIdx.x;
    if (i < SCAN_BLOCKS) { g_flag[i] = 0; }
    if (i < N_EDGES / 4) {
        int4 r = rows4[i];
        atomicAdd(&g_cnt[r.x], 1);
        atomicAdd(&g_cnt[r.y], 1);
        atomicAdd(&g_cnt[r.z], 1);
        atomicAdd(&g_cnt[r.w], 1);
    }
}

__global__ __launch_bounds__(SCAN_TPB) void k_scan() {
    int b = blockIdx.x;
    int tid = threadIdx.x;
    int lane = tid & 31;
    int wid = tid >> 5;
    int idx = b * NODES_PER_BLOCK + tid;

    int c = (tid < NODES_PER_BLOCK && idx < N_NODES) ? g_cnt[idx] : 0;

    int v = c;
#pragma unroll
    for (int off = 1; off < 32; off <<= 1) {
        int t = __shfl_up_sync(0xffffffffu, v, off);
        if (lane >= off) v += t;
    }
    __shared__ int ws[20];
    if (lane == 31) ws[wid] = v;
    __syncthreads();
    if (wid == 0) {
        int x = (lane < 20) ? ws[lane] : 0;
#pragma unroll
        for (int off = 1; off < 32; off <<= 1) {
            int t = __shfl_up_sync(0xffffffffu, x, off);
            if (lane >= off) x += t;
        }
        if (lane < 20) ws[lane] = x;
    }
    __syncthreads();
    int incl = v + ((wid > 0) ? ws[wid - 1] : 0);
    int btotal = ws[19];

    __shared__ int s_excl;
    if (tid == 0) {
        g_agg[b] = btotal;
        __threadfence();
        g_flag[b] = 1;
    }
    if (wid == 0) {
        int sum = 0;
        if (lane < b) {
            while (g_flag[lane] == 0) { }
            sum = g_agg[lane];
        }
#pragma unroll
        for (int off = 16; off > 0; off >>= 1)
            sum += __shfl_xor_sync(0xffffffffu, sum, off);
        if (lane == 0) s_excl = sum;
    }
    __syncthreads();
    int excl_blk = s_excl;

    if (tid < NODES_PER_BLOCK && idx < N_NODES) {
        int o = excl_blk + incl - c;
        g_rowptr[idx] = o;
        g_woff[idx] = o;
    }
    if (b == SCAN_BLOCKS - 1 && tid == 0)
        g_rowptr[N_NODES] = excl_blk + btotal;
}

__global__ void k_scatter(const int4* __restrict__ rows4, const int4* __restrict__ cols4) {
    int i = blockIdx.x * blockDim.x + threadIdx.x;
    if (i >= N_EDGES / 4) return;
    int4 r = rows4[i];
    int4 c = cols4[i];
    g_cols[atomicAdd(&g_woff[r.x], 1)] = c.x;
    g_cols[atomicAdd(&g_woff[r.y], 1)] = c.y;
    g_cols[atomicAdd(&g_woff[r.z], 1)] = c.z;
    g_cols[atomicAdd(&g_woff[r.w], 1)] = c.w;
}

// ---------------- fused SDDMM + softmax + SpMM (head-major, fp16 K/V) -------
// lane -> head h = lane/4, dim slice = (lane%4)*8. All loads coalesced.
// Score reduce = 2 shuffles in the 4-lane group; 1 exp per edge.
__global__ __launch_bounds__(256) void attn_kernel() {
    int gw = (blockIdx.x * blockDim.x + threadIdx.x) >> 5;
    int lane = threadIdx.x & 31;
    if (gw >= N_NODES) return;
    int row = gw;
    int p0 = g_rowptr[row];
    int p1 = g_rowptr[row + 1];

    const float scaling = 0.1767766952966369f;  // 1/sqrt(32)
    const float4* qp = (const float4*)(g_q + row * HID + lane * 8);
    float4 q0 = qp[0];
    float4 q1 = qp[1];
    float qv[8];
    qv[0] = q0.x * scaling; qv[1] = q0.y * scaling; qv[2] = q0.z * scaling; qv[3] = q0.w * scaling;
    qv[4] = q1.x * scaling; qv[5] = q1.y * scaling; qv[6] = q1.z * scaling; qv[7] = q1.w * scaling;

    float z = 0.f;
    float acc[8];
#pragma unroll
    for (int j = 0; j < 8; j++) acc[j] = 0.f;

    if (p0 < p1) {
        // 2-deep pipeline
        int col = g_cols[p0];
        uint4 kr = *(const uint4*)(g_kv + col * 512 + lane * 8);        // 8 K halves
        uint4 vr = *(const uint4*)(g_kv + col * 512 + 256 + lane * 8);  // 8 V halves

        for (int p = p0; p < p1; p++) {
            uint4 kc = kr, vc = vr;
            if (p + 1 < p1) {
                int col2 = g_cols[p + 1];
                kr = *(const uint4*)(g_kv + col2 * 512 + lane * 8);
                vr = *(const uint4*)(g_kv + col2 * 512 + 256 + lane * 8);
            }

            const __half2* kh = (const __half2*)&kc;
            float2 k01 = __half22float2(kh[0]);
            float2 k23 = __half22float2(kh[1]);
            float2 k45 = __half22float2(kh[2]);
            float2 k67 = __half22float2(kh[3]);

            float s = qv[0] * k01.x;
            s = fmaf(qv[1], k01.y, s);
            s = fmaf(qv[2], k23.x, s);
            s = fmaf(qv[3], k23.y, s);
            s = fmaf(qv[4], k45.x, s);
            s = fmaf(qv[5], k45.y, s);
            s = fmaf(qv[6], k67.x, s);
            s = fmaf(qv[7], k67.y, s);

            // reduce within the 4-lane head group
            s += __shfl_xor_sync(0xffffffffu, s, 1);
            s += __shfl_xor_sync(0xffffffffu, s, 2);

            float pr = __expf(s);
            z += pr;

            const __half2* vh = (const __half2*)&vc;
            float2 v01 = __half22float2(vh[0]);
            float2 v23 = __half22float2(vh[1]);
            float2 v45 = __half22float2(vh[2]);
            float2 v67 = __half22float2(vh[3]);
            acc[0] = fmaf(pr, v01.x, acc[0]);
            acc[1] = fmaf(pr, v01.y, acc[1]);
            acc[2] = fmaf(pr, v23.x, acc[2]);
            acc[3] = fmaf(pr, v23.y, acc[3]);
            acc[4] = fmaf(pr, v45.x, acc[4]);
            acc[5] = fmaf(pr, v45.y, acc[5]);
            acc[6] = fmaf(pr, v67.x, acc[6]);
            acc[7] = fmaf(pr, v67.y, acc[7]);
        }
    }

    float out[8];
    bool has = (p1 > p0);
    float inv = has ? 1.0f / z : 0.f;
#pragma unroll
    for (int j = 0; j < 8; j++) out[j] = acc[j] * inv;

    __align__(16) __nv_bfloat16 hi[8];
    __align__(16) __nv_bfloat16 lo[8];
#pragma unroll
    for (int j = 0; j < 8; j++) {
        hi[j] = __float2bfloat16(out[j]);
        lo[j] = __float2bfloat16(out[j] - __bfloat162float(hi[j]));
    }
    *(uint4*)(g_ao_hi + row * HID + lane * 8) = *(uint4*)hi;
    *(uint4*)(g_ao_lo + row * HID + lane * 8) = *(uint4*)lo;
}

// ---------------- launch ---------------------------------------------------
extern "C" void kernel_launch(void* const* d_in, const int* in_sizes, int n_in,
                              void* d_out, int out_size)
{
    const float* h  = (const float*)d_in[0];
    const float* Wq = (const float*)d_in[1];
    const float* bq = (const float*)d_in[2];
    const float* Wk = (const float*)d_in[3];
    const float* bk = (const float*)d_in[4];
    const float* Wv = (const float*)d_in[5];
    const float* bv = (const float*)d_in[6];
    const float* Wo = (const float*)d_in[7];
    const float* bo = (const float*)d_in[8];
    const int* rows = (const int*)d_in[9];
    const int* cols = (const int*)d_in[10];
    float* out = (float*)d_out;

    float *q, *bias3;
    __half* kv;
    __nv_bfloat16 *h_hi, *h_lo, *ao_hi, *ao_lo, *wc_hi, *wc_lo, *wo_hi, *wo_lo;
    cudaGetSymbolAddress((void**)&q,     g_q);
    cudaGetSymbolAddress((void**)&kv,    g_kv);
    cudaGetSymbolAddress((void**)&bias3, g_bias3);
    cudaGetSymbolAddress((void**)&h_hi,  g_h_hi);
    cudaGetSymbolAddress((void**)&h_lo,  g_h_lo);
    cudaGetSymbolAddress((void**)&ao_hi, g_ao_hi);
    cudaGetSymbolAddress((void**)&ao_lo, g_ao_lo);
    cudaGetSymbolAddress((void**)&wc_hi, g_wc_hi);
    cudaGetSymbolAddress((void**)&wc_lo, g_wc_lo);
    cudaGetSymbolAddress((void**)&wo_hi, g_wo_hi);
    cudaGetSymbolAddress((void**)&wo_lo, g_wo_lo);

    static int smem_set = 0;
    if (!smem_set) {
        cudaFuncSetAttribute(hgemm_split, cudaFuncAttributeMaxDynamicSharedMemorySize,
                             GEMM_SMEM_BYTES);
        smem_set = 1;
    }

    int n4h = (N_NODES * HID) / 4;

    k_prep<<<(n4h + 255) / 256, 256>>>((const float4*)h, (const float4*)Wq,
                                       (const float4*)Wk, (const float4*)Wv,
                                       (const float4*)Wo, bq, bk, bv, n4h);

    dim3 gqkv((N_NODES + BM - 1) / BM, NQKV / BN);
    hgemm_split<<<gqkv, 256, GEMM_SMEM_BYTES>>>(h_hi, h_lo, wc_hi, wc_lo, bias3,
                                                q, kv, N_NODES, NQKV);

    k_hist<<<(N_EDGES / 4 + 255) / 256, 256>>>((const int4*)rows);
    k_scan<<<SCAN_BLOCKS, SCAN_TPB>>>();
    k_scatter<<<(N_EDGES / 4 + 255) / 256, 256>>>((const int4*)rows, (const int4*)cols);

    attn_kernel<<<(N_NODES * 32 + 255) / 256, 256>>>();

    dim3 go((N_NODES + BM - 1) / BM, HID / BN);
    hgemm_split<<<go, 256, GEMM_SMEM_BYTES>>>(ao_hi, ao_lo, wo_hi, wo_lo, bo,
                                              out, (__half*)nullptr, N_NODES, HID);
}

// round 13
// speedup vs baseline: 1.0695x; 1.0689x over previous
#include <cuda_runtime.h>
#include <cuda_bf16.h>
#include <cuda_fp16.h>
#include <cstdint>
#include <stdint.h>
#include <math.h>

typedef unsigned int u32;

#define N_NODES 20000
#define N_EDGES 320000
#define HID 256
#define HEADS 8
#define HD 32
#define NQKV 768

#define SCAN_BLOCKS 32
#define SCAN_TPB 640           // 20 warps
#define NODES_PER_BLOCK 625    // 32 * 625 = 20000

// head-major permutation: logical col c (= d*8+h) -> h*32+d
__host__ __device__ __forceinline__ int hm_perm(int c) { return (c & 7) * 32 + (c >> 3); }

// ---------------- scratch (device globals; no allocation allowed) ----------
__device__ __align__(16) float  g_q[N_NODES * HID];          // Q fp32 (head-major)
__device__ __align__(16) __half g_kv[N_NODES * 512];         // K|V fp16 (head-major)
__device__ __align__(16) __nv_bfloat16 g_h_hi[N_NODES * HID];
__device__ __align__(16) __nv_bfloat16 g_h_lo[N_NODES * HID];
__device__ __align__(16) __nv_bfloat16 g_ao_hi[N_NODES * HID];  // head-major
__device__ __align__(16) __nv_bfloat16 g_ao_lo[N_NODES * HID];
__device__ __align__(16) __nv_bfloat16 g_wc_hi[HID * NQKV];  // cols permuted head-major
__device__ __align__(16) __nv_bfloat16 g_wc_lo[HID * NQKV];
__device__ __align__(16) __nv_bfloat16 g_wo_hi[HID * HID];   // rows permuted head-major
__device__ __align__(16) __nv_bfloat16 g_wo_lo[HID * HID];
__device__ __align__(16) float g_bias3[NQKV];                // permuted head-major
__device__ int g_cnt[N_NODES];          // zero at load (BSS); re-zeroed by k_scan
__device__ int g_rowptr[N_NODES + 1];
__device__ int g_woff[N_NODES];
__device__ int g_cols[N_EDGES];
__device__ volatile int g_agg[SCAN_BLOCKS];
__device__ volatile int g_flag[SCAN_BLOCKS];

// ---------------- fused prep: h split + W split(+permute) + bias -----------
// NOTE: does NOT touch g_cnt (CSR chain runs concurrently on another stream)
__global__ void k_prep(const float4* __restrict__ x,
                       const float4* __restrict__ Wq, const float4* __restrict__ Wk,
                       const float4* __restrict__ Wv, const float4* __restrict__ Wo,
                       const float* __restrict__ bq, const float* __restrict__ bk,
                       const float* __restrict__ bv, int n4h)
{
    int i = blockIdx.x * blockDim.x + threadIdx.x;
    if (i < NQKV) {
        int region = i >> 8;        // 0=q 1=k 2=v
        int c = i & 255;
        const float* b = (region == 0) ? bq : (region == 1) ? bk : bv;
        g_bias3[region * 256 + hm_perm(c)] = b[c];
    }

    if (i < 4 * 16384) {
        int widx = i >> 14;
        int j = i & 16383;
        const float4* src = (widx == 0) ? Wq : (widx == 1) ? Wk : (widx == 2) ? Wv : Wo;
        float4 v = src[j];
        float f[4];
        f[0] = v.x; f[1] = v.y; f[2] = v.z; f[3] = v.w;
        __align__(8) __nv_bfloat16 h[4];
        __align__(8) __nv_bfloat16 l[4];
#pragma unroll
        for (int t = 0; t < 4; t++) {
            h[t] = __float2bfloat16(f[t]);
            l[t] = __float2bfloat16(f[t] - __bfloat162float(h[t]));
        }
        int kr = j >> 6;        // row 0..255
        int n4 = j & 63;        // float4-col group
        if (widx < 3) {
            // permute COLUMNS to head-major: scattered 2B writes (tiny matrix)
#pragma unroll
            for (int t = 0; t < 4; t++) {
                int cc = hm_perm(n4 * 4 + t);
                int o = kr * NQKV + widx * 256 + cc;
                g_wc_hi[o] = h[t];
                g_wc_lo[o] = l[t];
            }
        } else {
            // permute ROWS to head-major: row stays contiguous -> coalesced
            int rr = hm_perm(kr);
            int o = rr * 64 + n4;
            ((uint2*)g_wo_hi)[o] = *(uint2*)h;
            ((uint2*)g_wo_lo)[o] = *(uint2*)l;
        }
    }

    if (i < n4h) {
        float4 v = x[i];
        float f[4];
        f[0] = v.x; f[1] = v.y; f[2] = v.z; f[3] = v.w;
        __align__(8) __nv_bfloat16 h[4];
        __align__(8) __nv_bfloat16 l[4];
#pragma unroll
        for (int j = 0; j < 4; j++) {
            h[j] = __float2bfloat16(f[j]);
            l[j] = __float2bfloat16(f[j] - __bfloat162float(h[j]));
        }
        ((uint2*)g_h_hi)[i] = *(uint2*)h;
        ((uint2*)g_h_lo)[i] = *(uint2*)l;
    }
}

// ---------------- split-bf16 tensor-core GEMM (cp.async 2-stage, 1 sync) ----
#define BM 128
#define BN 128
#define BK 32
#define STA 40
#define STW 136
#define NIT (HID / BK)
#define A_OFF(st, hl) (((st) * 2 + (hl)) * 5120)
#define W_OFF(st, hl) (20480 + ((st) * 2 + (hl)) * 4352)
#define GEMM_SMEM_BYTES ((20480 + 17408) * 2)

__device__ __forceinline__ void ldm_x4(u32* r, u32 addr) {
    asm volatile("ldmatrix.sync.aligned.m8n8.x4.shared.b16 {%0,%1,%2,%3}, [%4];"
                 : "=r"(r[0]), "=r"(r[1]), "=r"(r[2]), "=r"(r[3]) : "r"(addr));
}
__device__ __forceinline__ void ldm_x4t(u32* r, u32 addr) {
    asm volatile("ldmatrix.sync.aligned.m8n8.x4.trans.shared.b16 {%0,%1,%2,%3}, [%4];"
                 : "=r"(r[0]), "=r"(r[1]), "=r"(r[2]), "=r"(r[3]) : "r"(addr));
}
__device__ __forceinline__ void mma16816(float* c, const u32* a, const u32* b) {
    asm volatile("mma.sync.aligned.m16n8k16.row.col.f32.bf16.bf16.f32 "
                 "{%0,%1,%2,%3}, {%4,%5,%6,%7}, {%8,%9}, {%0,%1,%2,%3};"
                 : "+f"(c[0]), "+f"(c[1]), "+f"(c[2]), "+f"(c[3])
                 : "r"(a[0]), "r"(a[1]), "r"(a[2]), "r"(a[3]), "r"(b[0]), "r"(b[1]));
}
__device__ __forceinline__ void cpa16(u32 dst, const void* src, int bytes) {
    asm volatile("cp.async.cg.shared.global [%0], [%1], 16, %2;"
                 :: "r"(dst), "l"(src), "r"(bytes));
}

__global__ __launch_bounds__(256) void hgemm_split(
    const __nv_bfloat16* __restrict__ Ahi, const __nv_bfloat16* __restrict__ Alo,
    const __nv_bfloat16* __restrict__ Whi, const __nv_bfloat16* __restrict__ Wlo,
    const float* __restrict__ bias, float* __restrict__ Cq, __half* __restrict__ Ckv,
    int M, int NTOT)
{
    extern __shared__ __align__(16) __nv_bfloat16 smem[];
    u32 smB = (u32)__cvta_generic_to_shared(smem);

    int tid = threadIdx.x;
    int lane = tid & 31;
    int wid = tid >> 5;
    int mwarp = (wid >> 2) * 64;
    int nwarp = (wid & 3) * 32;
    int blockM = blockIdx.x * BM;
    int blockN = blockIdx.y * BN;

    int rA[2], kcA[2], grA[2], krW[2], ncW[2];
#pragma unroll
    for (int it = 0; it < 2; it++) {
        int idx = tid + it * 256;
        rA[it] = idx >> 2;  kcA[it] = idx & 3;  grA[it] = blockM + rA[it];
        krW[it] = idx >> 4; ncW[it] = idx & 15;
    }

    float acc[4][4][4];
#pragma unroll
    for (int mt = 0; mt < 4; mt++)
#pragma unroll
        for (int nt = 0; nt < 4; nt++)
#pragma unroll
            for (int j = 0; j < 4; j++) acc[mt][nt][j] = 0.f;

    int rowA = (lane & 7) + ((lane >> 3) & 1) * 8;
    int offA = rowA * (STA * 2) + (lane >> 4) * 16;
    int offB4 = ((lane & 7) + ((lane >> 3) & 1) * 8) * (STW * 2) + ((lane >> 4) & 1) * 16;

#define LOAD_STAGE(st, k0base)                                                     \
    do {                                                                           \
        _Pragma("unroll")                                                          \
        for (int it = 0; it < 2; it++) {                                           \
            int pb = (grA[it] < M) ? 16 : 0;                                       \
            u32 dAh = smB + (u32)(A_OFF(st, 0) + rA[it] * STA + kcA[it] * 8) * 2;  \
            u32 dAl = smB + (u32)(A_OFF(st, 1) + rA[it] * STA + kcA[it] * 8) * 2;  \
            cpa16(dAh, Ahi + grA[it] * HID + (k0base) + kcA[it] * 8, pb);          \
            cpa16(dAl, Alo + grA[it] * HID + (k0base) + kcA[it] * 8, pb);          \
            u32 dWh = smB + (u32)(W_OFF(st, 0) + krW[it] * STW + ncW[it] * 8) * 2; \
            u32 dWl = smB + (u32)(W_OFF(st, 1) + krW[it] * STW + ncW[it] * 8) * 2; \
            cpa16(dWh, Whi + ((k0base) + krW[it]) * NTOT + blockN + ncW[it] * 8, 16); \
            cpa16(dWl, Wlo + ((k0base) + krW[it]) * NTOT + blockN + ncW[it] * 8, 16); \
        }                                                                          \
        asm volatile("cp.async.commit_group;");                                    \
    } while (0)

#define MMA_STAGE(st)                                                              \
    do {                                                                           \
        _Pragma("unroll")                                                          \
        for (int kk = 0; kk < 2; kk++) {                                           \
            u32 ahi[4][4], alo[4][4], bhi[4][2], blo[4][2];                        \
            _Pragma("unroll")                                                      \
            for (int mt = 0; mt < 4; mt++) {                                       \
                u32 o = (u32)((mwarp + mt * 16) * (STA * 2) + kk * 32 + offA);     \
                ldm_x4(ahi[mt], smB + (u32)A_OFF(st, 0) * 2 + o);                  \
                ldm_x4(alo[mt], smB + (u32)A_OFF(st, 1) * 2 + o);                  \
            }                                                                      \
            _Pragma("unroll")                                                      \
            for (int np = 0; np < 2; np++) {                                       \
                u32 o = (u32)(kk * 16 * (STW * 2) + offB4 + (nwarp + np * 16) * 2);\
                u32 rh[4], rl[4];                                                  \
                ldm_x4t(rh, smB + (u32)W_OFF(st, 0) * 2 + o);                      \
                ldm_x4t(rl, smB + (u32)W_OFF(st, 1) * 2 + o);                      \
                bhi[np * 2][0] = rh[0]; bhi[np * 2][1] = rh[1];                    \
                bhi[np * 2 + 1][0] = rh[2]; bhi[np * 2 + 1][1] = rh[3];            \
                blo[np * 2][0] = rl[0]; blo[np * 2][1] = rl[1];                    \
                blo[np * 2 + 1][0] = rl[2]; blo[np * 2 + 1][1] = rl[3];            \
            }                                                                      \
            _Pragma("unroll")                                                      \
            for (int mt = 0; mt < 4; mt++) {                                       \
                _Pragma("unroll")                                                  \
                for (int nt = 0; nt < 4; nt++) {                                   \
                    mma16816(acc[mt][nt], ahi[mt], bhi[nt]);                       \
                    mma16816(acc[mt][nt], ahi[mt], blo[nt]);                       \
                    mma16816(acc[mt][nt], alo[mt], bhi[nt]);                       \
                }                                                                  \
            }                                                                      \
        }                                                                          \
    } while (0)

    LOAD_STAGE(0, 0);
#pragma unroll 1
    for (int i = 0; i < NIT; i++) {
        asm volatile("cp.async.wait_group 0;");
        __syncthreads();
        if (i + 1 < NIT) LOAD_STAGE((i + 1) & 1, (i + 1) * BK);
        MMA_STAGE(i & 1);
    }

    // epilogue: + bias, route Q (fp32) vs KV (fp16)
    int g = lane >> 2;
    int t4 = lane & 3;
#pragma unroll
    for (int mt = 0; mt < 4; mt++) {
        int row0 = blockM + mwarp + mt * 16 + g;
        int row1 = row0 + 8;
#pragma unroll
        for (int nt = 0; nt < 4; nt++) {
            int col = blockN + nwarp + nt * 8 + t4 * 2;
            float b0 = bias[col];
            float b1 = bias[col + 1];
            float c00 = acc[mt][nt][0] + b0, c01 = acc[mt][nt][1] + b1;
            float c10 = acc[mt][nt][2] + b0, c11 = acc[mt][nt][3] + b1;
            if (col < 256) {
                if (row0 < M) *(float2*)(Cq + row0 * 256 + col) = make_float2(c00, c01);
                if (row1 < M) *(float2*)(Cq + row1 * 256 + col) = make_float2(c10, c11);
            } else {
                int kc = col - 256;
                if (row0 < M) *(__half2*)(Ckv + row0 * 512 + kc) = __floats2half2_rn(c00, c01);
                if (row1 < M) *(__half2*)(Ckv + row1 * 512 + kc) = __floats2half2_rn(c10, c11);
            }
        }
    }
}

// ---------------- CSR build (independent stream) ----------------------------
__global__ void k_hist(const int4* __restrict__ rows4) {
    int i = blockIdx.x * blockDim.x + threadIdx.x;
    if (i < SCAN_BLOCKS) { g_flag[i] = 0; }
    if (i < N_EDGES / 4) {
        int4 r = rows4[i];
        atomicAdd(&g_cnt[r.x], 1);
        atomicAdd(&g_cnt[r.y], 1);
        atomicAdd(&g_cnt[r.z], 1);
        atomicAdd(&g_cnt[r.w], 1);
    }
}

__global__ __launch_bounds__(SCAN_TPB) void k_scan() {
    int b = blockIdx.x;
    int tid = threadIdx.x;
    int lane = tid & 31;
    int wid = tid >> 5;
    int idx = b * NODES_PER_BLOCK + tid;

    bool active = (tid < NODES_PER_BLOCK && idx < N_NODES);
    int c = active ? g_cnt[idx] : 0;
    if (active) g_cnt[idx] = 0;   // re-zero for the next graph replay's k_hist

    int v = c;
#pragma unroll
    for (int off = 1; off < 32; off <<= 1) {
        int t = __shfl_up_sync(0xffffffffu, v, off);
        if (lane >= off) v += t;
    }
    __shared__ int ws[20];
    if (lane == 31) ws[wid] = v;
    __syncthreads();
    if (wid == 0) {
        int x = (lane < 20) ? ws[lane] : 0;
#pragma unroll
        for (int off = 1; off < 32; off <<= 1) {
            int t = __shfl_up_sync(0xffffffffu, x, off);
            if (lane >= off) x += t;
        }
        if (lane < 20) ws[lane] = x;
    }
    __syncthreads();
    int incl = v + ((wid > 0) ? ws[wid - 1] : 0);
    int btotal = ws[19];

    __shared__ int s_excl;
    if (tid == 0) {
        g_agg[b] = btotal;
        __threadfence();
        g_flag[b] = 1;
    }
    if (wid == 0) {
        int sum = 0;
        if (lane < b) {
            while (g_flag[lane] == 0) { }
            sum = g_agg[lane];
        }
#pragma unroll
        for (int off = 16; off > 0; off >>= 1)
            sum += __shfl_xor_sync(0xffffffffu, sum, off);
        if (lane == 0) s_excl = sum;
    }
    __syncthreads();
    int excl_blk = s_excl;

    if (active) {
        int o = excl_blk + incl - c;
        g_rowptr[idx] = o;
        g_woff[idx] = o;
    }
    if (b == SCAN_BLOCKS - 1 && tid == 0)
        g_rowptr[N_NODES] = excl_blk + btotal;
}

__global__ void k_scatter(const int4* __restrict__ rows4, const int4* __restrict__ cols4) {
    int i = blockIdx.x * blockDim.x + threadIdx.x;
    if (i >= N_EDGES / 4) return;
    int4 r = rows4[i];
    int4 c = cols4[i];
    g_cols[atomicAdd(&g_woff[r.x], 1)] = c.x;
    g_cols[atomicAdd(&g_woff[r.y], 1)] = c.y;
    g_cols[atomicAdd(&g_woff[r.z], 1)] = c.z;
    g_cols[atomicAdd(&g_woff[r.w], 1)] = c.w;
}

// ---------------- fused SDDMM + softmax + SpMM (head-major, fp16 K/V) -------
__global__ __launch_bounds__(256) void attn_kernel() {
    int gw = (blockIdx.x * blockDim.x + threadIdx.x) >> 5;
    int lane = threadIdx.x & 31;
    if (gw >= N_NODES) return;
    int row = gw;
    int p0 = g_rowptr[row];
    int p1 = g_rowptr[row + 1];

    const float scaling = 0.1767766952966369f;  // 1/sqrt(32)
    const float4* qp = (const float4*)(g_q + row * HID + lane * 8);
    float4 q0 = qp[0];
    float4 q1 = qp[1];
    float qv[8];
    qv[0] = q0.x * scaling; qv[1] = q0.y * scaling; qv[2] = q0.z * scaling; qv[3] = q0.w * scaling;
    qv[4] = q1.x * scaling; qv[5] = q1.y * scaling; qv[6] = q1.z * scaling; qv[7] = q1.w * scaling;

    float z = 0.f;
    float acc[8];
#pragma unroll
    for (int j = 0; j < 8; j++) acc[j] = 0.f;

    if (p0 < p1) {
        int col = g_cols[p0];
        uint4 kr = *(const uint4*)(g_kv + col * 512 + lane * 8);
        uint4 vr = *(const uint4*)(g_kv + col * 512 + 256 + lane * 8);

        for (int p = p0; p < p1; p++) {
            uint4 kc = kr, vc = vr;
            if (p + 1 < p1) {
                int col2 = g_cols[p + 1];
                kr = *(const uint4*)(g_kv + col2 * 512 + lane * 8);
                vr = *(const uint4*)(g_kv + col2 * 512 + 256 + lane * 8);
            }

            const __half2* kh = (const __half2*)&kc;
            float2 k01 = __half22float2(kh[0]);
            float2 k23 = __half22float2(kh[1]);
            float2 k45 = __half22float2(kh[2]);
            float2 k67 = __half22float2(kh[3]);

            float s = qv[0] * k01.x;
            s = fmaf(qv[1], k01.y, s);
            s = fmaf(qv[2], k23.x, s);
            s = fmaf(qv[3], k23.y, s);
            s = fmaf(qv[4], k45.x, s);
            s = fmaf(qv[5], k45.y, s);
            s = fmaf(qv[6], k67.x, s);
            s = fmaf(qv[7], k67.y, s);

            s += __shfl_xor_sync(0xffffffffu, s, 1);
            s += __shfl_xor_sync(0xffffffffu, s, 2);

            float pr = __expf(s);
            z += pr;

            const __half2* vh = (const __half2*)&vc;
            float2 v01 = __half22float2(vh[0]);
            float2 v23 = __half22float2(vh[1]);
            float2 v45 = __half22float2(vh[2]);
            float2 v67 = __half22float2(vh[3]);
            acc[0] = fmaf(pr, v01.x, acc[0]);
            acc[1] = fmaf(pr, v01.y, acc[1]);
            acc[2] = fmaf(pr, v23.x, acc[2]);
            acc[3] = fmaf(pr, v23.y, acc[3]);
            acc[4] = fmaf(pr, v45.x, acc[4]);
            acc[5] = fmaf(pr, v45.y, acc[5]);
            acc[6] = fmaf(pr, v67.x, acc[6]);
            acc[7] = fmaf(pr, v67.y, acc[7]);
        }
    }

    float out[8];
    bool has = (p1 > p0);
    float inv = has ? 1.0f / z : 0.f;
#pragma unroll
    for (int j = 0; j < 8; j++) out[j] = acc[j] * inv;

    __align__(16) __nv_bfloat16 hi[8];
    __align__(16) __nv_bfloat16 lo[8];
#pragma unroll
    for (int j = 0; j < 8; j++) {
        hi[j] = __float2bfloat16(out[j]);
        lo[j] = __float2bfloat16(out[j] - __bfloat162float(hi[j]));
    }
    *(uint4*)(g_ao_hi + row * HID + lane * 8) = *(uint4*)hi;
    *(uint4*)(g_ao_lo + row * HID + lane * 8) = *(uint4*)lo;
}

// ---------------- launch ---------------------------------------------------
extern "C" void kernel_launch(void* const* d_in, const int* in_sizes, int n_in,
                              void* d_out, int out_size)
{
    const float* h  = (const float*)d_in[0];
    const float* Wq = (const float*)d_in[1];
    const float* bq = (const float*)d_in[2];
    const float* Wk = (const float*)d_in[3];
    const float* bk = (const float*)d_in[4];
    const float* Wv = (const float*)d_in[5];
    const float* bv = (const float*)d_in[6];
    const float* Wo = (const float*)d_in[7];
    const float* bo = (const float*)d_in[8];
    const int* rows = (const int*)d_in[9];
    const int* cols = (const int*)d_in[10];
    float* out = (float*)d_out;

    float *q, *bias3;
    __half* kv;
    __nv_bfloat16 *h_hi, *h_lo, *ao_hi, *ao_lo, *wc_hi, *wc_lo, *wo_hi, *wo_lo;
    cudaGetSymbolAddress((void**)&q,     g_q);
    cudaGetSymbolAddress((void**)&kv,    g_kv);
    cudaGetSymbolAddress((void**)&bias3, g_bias3);
    cudaGetSymbolAddress((void**)&h_hi,  g_h_hi);
    cudaGetSymbolAddress((void**)&h_lo,  g_h_lo);
    cudaGetSymbolAddress((void**)&ao_hi, g_ao_hi);
    cudaGetSymbolAddress((void**)&ao_lo, g_ao_lo);
    cudaGetSymbolAddress((void**)&wc_hi, g_wc_hi);
    cudaGetSymbolAddress((void**)&wc_lo, g_wc_lo);
    cudaGetSymbolAddress((void**)&wo_hi, g_wo_hi);
    cudaGetSymbolAddress((void**)&wo_lo, g_wo_lo);

    static int init_done = 0;
    static cudaStream_t s2;
    static cudaEvent_t evFork, evJoin;
    if (!init_done) {
        cudaFuncSetAttribute(hgemm_split, cudaFuncAttributeMaxDynamicSharedMemorySize,
                             GEMM_SMEM_BYTES);
        cudaStreamCreateWithFlags(&s2, cudaStreamNonBlocking);
        cudaEventCreateWithFlags(&evFork, cudaEventDisableTiming);
        cudaEventCreateWithFlags(&evJoin, cudaEventDisableTiming);
        init_done = 1;
    }

    int n4h = (N_NODES * HID) / 4;

    // fork: CSR chain on s2, projection chain on the capture (default) stream
    cudaEventRecord(evFork, 0);
    cudaStreamWaitEvent(s2, evFork, 0);

    // --- stream 0: prep -> fused QKV GEMM ---
    k_prep<<<(n4h + 255) / 256, 256>>>((const float4*)h, (const float4*)Wq,
                                       (const float4*)Wk, (const float4*)Wv,
                                       (const float4*)Wo, bq, bk, bv, n4h);
    dim3 gqkv((N_NODES + BM - 1) / BM, NQKV / BN);
    hgemm_split<<<gqkv, 256, GEMM_SMEM_BYTES>>>(h_hi, h_lo, wc_hi, wc_lo, bias3,
                                                q, kv, N_NODES, NQKV);

    // --- stream s2: hist -> scan -> scatter (depends only on rows/cols) ---
    k_hist<<<(N_EDGES / 4 + 255) / 256, 256, 0, s2>>>((const int4*)rows);
    k_scan<<<SCAN_BLOCKS, SCAN_TPB, 0, s2>>>();
    k_scatter<<<(N_EDGES / 4 + 255) / 256, 256, 0, s2>>>((const int4*)rows, (const int4*)cols);
    cudaEventRecord(evJoin, s2);

    // join: attention needs QKV (stream 0 order) + CSR (event)
    cudaStreamWaitEvent(0, evJoin, 0);
    attn_kernel<<<(N_NODES * 32 + 255) / 256, 256>>>();

    dim3 go((N_NODES + BM - 1) / BM, HID / BN);
    hgemm_split<<<go, 256, GEMM_SMEM_BYTES>>>(ao_hi, ao_lo, wo_hi, wo_lo, bo,
                                              out, (__half*)nullptr, N_NODES, HID);
}